// round 6
// baseline (speedup 1.0000x reference)
#include <cuda_runtime.h>
#include <cstdint>

// SDDMM: out[i] = mask_vals[i] + dot(mat1[rows[i], :], mat2[:, cols[i]])
// Inputs: mask_vals f32[1e6], rows i32[1e6], cols i32[1e6],
//         mat1 f32[8192,128], mat2 f32[128,8192]   Output: f32[1e6]

#define NNZ  1000000
#define MDIM 8192
#define NDIM 8192
#define KDIM 128

#define RBBITS 8                       // 256 rows per rowblock
#define NRB    (MDIM >> RBBITS)        // 32 rowblocks
#define NBUCK  (NRB * NDIM)            // 262144 buckets: key = rowblock*8192+col
#define SCAN_BLK   256
#define SCAN_CHUNK (NBUCK / SCAN_BLK)  // 1024

#define SDDMM_BLOCKS 592               // 4 per SM
#define CHUNK 1692                     // ceil(NNZ/592) rounded to mult of 4

// Static scratch (no allocations anywhere)
__device__ float        g_mat2T[(size_t)NDIM * KDIM];
__device__ int          g_buck[NBUCK];
__device__ int          g_cursor[NBUCK];
__device__ int          g_part[SCAN_BLK];
__device__ unsigned int g_rc[NNZ];     // packed (row<<13)|col
__device__ int          g_perm[NNZ];   // original nnz index

// ---------------------------------------------------------------------------
// Transpose mat2 [K, N] -> g_mat2T [N, K]
// ---------------------------------------------------------------------------
__global__ void transpose_k(const float* __restrict__ mat2) {
    __shared__ float tile[32][33];
    const int n0 = blockIdx.x * 32;
    const int k0 = blockIdx.y * 32;
    #pragma unroll
    for (int r = threadIdx.y; r < 32; r += 8)
        tile[r][threadIdx.x] = mat2[(size_t)(k0 + r) * NDIM + n0 + threadIdx.x];
    __syncthreads();
    #pragma unroll
    for (int r = threadIdx.y; r < 32; r += 8)
        g_mat2T[(size_t)(n0 + r) * KDIM + k0 + threadIdx.x] = tile[threadIdx.x][r];
}

// ---------------------------------------------------------------------------
// Counting sort by key = (row>>8, col)
// ---------------------------------------------------------------------------
__global__ void zero_k() {
    g_buck[blockIdx.x * blockDim.x + threadIdx.x] = 0;
}

__device__ __forceinline__ int make_key(int r, int c) {
    return ((r >> RBBITS) << 13) | c;
}

__global__ void hist_k(const int* __restrict__ rows,
                       const int* __restrict__ cols) {
    const int i = blockIdx.x * blockDim.x + threadIdx.x;
    if (i < NNZ) atomicAdd(&g_buck[make_key(rows[i], cols[i])], 1);
}

// Pass 1: per-block sums of 1024-element chunks
__global__ void scan1_k() {
    __shared__ int sh[32];
    const int t = threadIdx.x;
    int v = g_buck[blockIdx.x * SCAN_CHUNK + t];
    #pragma unroll
    for (int o = 16; o > 0; o >>= 1) v += __shfl_xor_sync(~0u, v, o);
    if ((t & 31) == 0) sh[t >> 5] = v;
    __syncthreads();
    if (t < 32) {
        int s = sh[t];
        #pragma unroll
        for (int o = 16; o > 0; o >>= 1) s += __shfl_xor_sync(~0u, s, o);
        if (t == 0) g_part[blockIdx.x] = s;
    }
}

// Pass 2: exclusive scan of the 256 partials (single block)
__global__ void scan2_k() {
    __shared__ int sh[SCAN_BLK];
    const int t = threadIdx.x;
    const int v = g_part[t];
    sh[t] = v;
    __syncthreads();
    for (int off = 1; off < SCAN_BLK; off <<= 1) {
        int x = (t >= off) ? sh[t - off] : 0;
        __syncthreads();
        sh[t] += x;
        __syncthreads();
    }
    g_part[t] = sh[t] - v;   // exclusive
}

// Pass 3: per-block exclusive scan + offset -> cursors
__global__ void scan3_k() {
    __shared__ int sh[SCAN_CHUNK];
    const int t = threadIdx.x;
    const int idx = blockIdx.x * SCAN_CHUNK + t;
    const int v = g_buck[idx];
    sh[t] = v;
    __syncthreads();
    for (int off = 1; off < SCAN_CHUNK; off <<= 1) {
        int x = (t >= off) ? sh[t - off] : 0;
        __syncthreads();
        sh[t] += x;
        __syncthreads();
    }
    g_cursor[idx] = sh[t] - v + g_part[blockIdx.x];
}

__global__ void scatter_k(const int* __restrict__ rows,
                          const int* __restrict__ cols) {
    const int i = blockIdx.x * blockDim.x + threadIdx.x;
    if (i >= NNZ) return;
    const int r = rows[i];
    const int c = cols[i];
    const int p = atomicAdd(&g_cursor[make_key(r, c)], 1);
    g_rc[p]   = ((unsigned int)r << 13) | (unsigned int)c;
    g_perm[p] = i;
}

// ---------------------------------------------------------------------------
// SDDMM over (rowblock, col)-sorted nnz.
// Each block owns a contiguous chunk of sorted nnz (rows stay inside one
// 256-row block -> 128KB row working set lives in L1; equal cols are
// adjacent -> LDG dedup within the warp iteration).
// 8 lanes per nnz, 4 consecutive nnz per warp-iteration.
// ---------------------------------------------------------------------------
__global__ void __launch_bounds__(256)
sddmm_k(const float* __restrict__ mask_vals,
        const float* __restrict__ mat1,
        float* __restrict__ out) {
    const int lane = threadIdx.x & 31;
    const int sub  = lane & 7;
    const int grp  = lane >> 3;
    const int w    = threadIdx.x >> 5;         // warp in block (0..7)

    const int start = blockIdx.x * CHUNK;
    const int end   = min(start + CHUNK, NNZ);

    for (int base = start + w * 4; base < end; base += 8 * 4) {
        const int j     = base + grp;
        const bool live = (j < end);
        const unsigned int rc = live ? g_rc[j] : 0u;
        const int r = rc >> 13;
        const int c = rc & 0x1FFF;

        const float4* __restrict__ a4 =
            reinterpret_cast<const float4*>(mat1 + (size_t)r * KDIM);
        const float4* __restrict__ b4 =
            reinterpret_cast<const float4*>(g_mat2T + (size_t)c * KDIM);

        const float4 a0 = a4[sub];
        const float4 b0 = b4[sub];
        const float4 a1 = a4[sub + 8];
        const float4 b1 = b4[sub + 8];
        const float4 a2 = a4[sub + 16];
        const float4 b2 = b4[sub + 16];
        const float4 a3 = a4[sub + 24];
        const float4 b3 = b4[sub + 24];

        float s = a0.x * b0.x;
        s = fmaf(a0.y, b0.y, s); s = fmaf(a0.z, b0.z, s); s = fmaf(a0.w, b0.w, s);
        s = fmaf(a1.x, b1.x, s); s = fmaf(a1.y, b1.y, s);
        s = fmaf(a1.z, b1.z, s); s = fmaf(a1.w, b1.w, s);
        s = fmaf(a2.x, b2.x, s); s = fmaf(a2.y, b2.y, s);
        s = fmaf(a2.z, b2.z, s); s = fmaf(a2.w, b2.w, s);
        s = fmaf(a3.x, b3.x, s); s = fmaf(a3.y, b3.y, s);
        s = fmaf(a3.z, b3.z, s); s = fmaf(a3.w, b3.w, s);

        s += __shfl_xor_sync(0xFFFFFFFFu, s, 4);
        s += __shfl_xor_sync(0xFFFFFFFFu, s, 2);
        s += __shfl_xor_sync(0xFFFFFFFFu, s, 1);

        if (sub == 0 && live) {
            const int i = g_perm[j];
            out[i] = mask_vals[i] + s;
        }
    }
}

extern "C" void kernel_launch(void* const* d_in, const int* in_sizes, int n_in,
                              void* d_out, int out_size) {
    const float* mask_vals = (const float*)d_in[0];
    const int*   rows      = (const int*)d_in[1];
    const int*   cols      = (const int*)d_in[2];
    const float* mat1      = (const float*)d_in[3];
    const float* mat2      = (const float*)d_in[4];
    float*       out       = (float*)d_out;

    transpose_k<<<dim3(NDIM / 32, KDIM / 32), dim3(32, 8)>>>(mat2);

    zero_k<<<NBUCK / 1024, 1024>>>();
    hist_k<<<(NNZ + 255) / 256, 256>>>(rows, cols);
    scan1_k<<<SCAN_BLK, SCAN_CHUNK>>>();
    scan2_k<<<1, SCAN_BLK>>>();
    scan3_k<<<SCAN_BLK, SCAN_CHUNK>>>();
    scatter_k<<<(NNZ + 255) / 256, 256>>>(rows, cols);

    sddmm_k<<<SDDMM_BLOCKS, 256>>>(mask_vals, mat1, out);
}